// round 13
// baseline (speedup 1.0000x reference)
#include <cuda_runtime.h>
#include <cuda_fp16.h>

// Output layout (flattened jax pytree, each region N*16 f32 = n4 float4s):
//   region 0: -x + tanh(agg)   region 1: x   region 2: -x
//   region 3: agg (f32, from fp16 accumulator)   region 4: tanh(agg)
//
// R13 = R11 edge kernel (best: ILP=2, plain __ldg) + overhead trims:
//   - g_agg16 zeroed by cudaMemsetAsync (overlaps; pack kernel slims down)
//   - final kernel does 2 float4/thread (latency-bound)

#define MAX_N 100000
__device__ uint4 g_x16[MAX_N * 2];    // fp16 copy of x: 32 B/node
__device__ uint4 g_agg16[MAX_N * 2];  // fp16 accumulators: 32 B/node

__device__ __forceinline__ unsigned pack_h2(float a, float b) {
    __half2 h = __floats2half2_rn(a, b);
    return *reinterpret_cast<unsigned*>(&h);
}

__device__ __forceinline__ float2 h2f(unsigned u) {
    __half2 h = *reinterpret_cast<__half2*>(&u);
    return __half22float2(h);
}

// Pack x -> fp16 (agg zeroing moved to a memset node).
__global__ void pack_kernel(const float4* __restrict__ x, int n4) {
    int i = blockIdx.x * blockDim.x + threadIdx.x;
    if (i >= n4) return;
    float4 v = __ldg(&x[i]);
    ((uint2*)g_x16)[i] = make_uint2(pack_h2(v.x, v.y), pack_h2(v.z, v.w));
}

__device__ __forceinline__ void msgs(float we, const uint4& ur, const uint4& uc,
                                     unsigned& p0, unsigned& p1,
                                     unsigned& p2, unsigned& p3) {
    float2 a0 = h2f(ur.x), a1 = h2f(ur.y), a2 = h2f(ur.z), a3 = h2f(ur.w);
    float2 b0 = h2f(uc.x), b1 = h2f(uc.y), b2 = h2f(uc.z), b3 = h2f(uc.w);
    p0 = pack_h2(we * __sinf(a0.x - b0.x), we * __sinf(a0.y - b0.y));
    p1 = pack_h2(we * __sinf(a1.x - b1.x), we * __sinf(a1.y - b1.y));
    p2 = pack_h2(we * __sinf(a2.x - b2.x), we * __sinf(a2.y - b2.y));
    p3 = pack_h2(we * __sinf(a3.x - b3.x), we * __sinf(a3.y - b3.y));
}

#define RED_V4F16X2(dst, p0, p1, p2, p3)                                    \
    asm volatile("red.global.add.noftz.v4.f16x2 [%0], {%1, %2, %3, %4};"    \
                 :: "l"(dst), "r"(p0), "r"(p1), "r"(p2), "r"(p3) : "memory")

// Edge scatter (2 edges/thread, 2 threads/edge, lane-pair sector-combined)
// + region-1/2 copies fused.
__global__ void edge_copy_kernel(const float4* __restrict__ x,
                                 const int* __restrict__ row,
                                 const int* __restrict__ col,
                                 const float* __restrict__ w,
                                 float4* __restrict__ out,
                                 int n4, int E, int edgeBlocks) {
    if (blockIdx.x >= edgeBlocks) {
        int i = (blockIdx.x - edgeBlocks) * blockDim.x + threadIdx.x;
        if (i < n4) {
            float4 v = __ldg(&x[i]);
            __stcs(&out[n4 + i], v);                                      // region 1
            __stcs(&out[2 * n4 + i],
                   make_float4(-v.x, -v.y, -v.z, -v.w));                  // region 2
        }
        return;
    }

    int t = blockIdx.x * blockDim.x + threadIdx.x;
    int p = t >> 1;                  // pair index: edges p and p+Eh
    int h = t & 1;                   // lane-pair half: 8 dims each
    int Eh = (E + 1) >> 1;
    if (p >= Eh) return;
    int eB = p + Eh;
    bool hasB = eB < E;

    int   rA = __ldg(&row[p]);
    int   cA = __ldg(&col[p]);
    float wA = __ldg(&w[p]);
    int rB = rA, cB = cA; float wB = 0.f;
    if (hasB) { rB = __ldg(&row[eB]); cB = __ldg(&col[eB]); wB = __ldg(&w[eB]); }

    // Front-batch 4 independent 16 B gathers (MLP=4); lanes 2i/2i+1 of an
    // edge hit the same 32 B record -> 1 combined wavefront per endpoint.
    uint4 urA = __ldg(&g_x16[rA * 2 + h]);
    uint4 ucA = __ldg(&g_x16[cA * 2 + h]);
    uint4 urB = __ldg(&g_x16[rB * 2 + h]);
    uint4 ucB = __ldg(&g_x16[cB * 2 + h]);

    unsigned pa0, pa1, pa2, pa3, pb0, pb1, pb2, pb3;
    msgs(wA, urA, ucA, pa0, pa1, pa2, pa3);
    msgs(wB, urB, ucB, pb0, pb1, pb2, pb3);

    RED_V4F16X2(&g_agg16[cA * 2 + h], pa0, pa1, pa2, pa3);
    if (hasB) RED_V4F16X2(&g_agg16[cB * 2 + h], pb0, pb1, pb2, pb3);
}

// Final: 2 float4/thread (latency-bound), front-batched loads.
__global__ void final_kernel(const float4* __restrict__ x,
                             float4* __restrict__ out, int n4) {
    int i0 = blockIdx.x * (blockDim.x * 2) + threadIdx.x;
    int i1 = i0 + blockDim.x;
    bool has0 = i0 < n4, has1 = i1 < n4;

    uint2 g0, g1; float4 v0, v1;
    if (has0) { g0 = ((const uint2*)g_agg16)[i0]; v0 = __ldg(&x[i0]); }
    if (has1) { g1 = ((const uint2*)g_agg16)[i1]; v1 = __ldg(&x[i1]); }

    if (has0) {
        float2 lo = h2f(g0.x), hi = h2f(g0.y);
        float4 a = make_float4(lo.x, lo.y, hi.x, hi.y);
        float4 t = make_float4(tanhf(a.x), tanhf(a.y), tanhf(a.z), tanhf(a.w));
        __stcs(&out[3 * n4 + i0], a);
        __stcs(&out[4 * n4 + i0], t);
        __stcs(&out[i0], make_float4(t.x - v0.x, t.y - v0.y,
                                     t.z - v0.z, t.w - v0.w));
    }
    if (has1) {
        float2 lo = h2f(g1.x), hi = h2f(g1.y);
        float4 a = make_float4(lo.x, lo.y, hi.x, hi.y);
        float4 t = make_float4(tanhf(a.x), tanhf(a.y), tanhf(a.z), tanhf(a.w));
        __stcs(&out[3 * n4 + i1], a);
        __stcs(&out[4 * n4 + i1], t);
        __stcs(&out[i1], make_float4(t.x - v1.x, t.y - v1.y,
                                     t.z - v1.z, t.w - v1.w));
    }
}

extern "C" void kernel_launch(void* const* d_in, const int* in_sizes, int n_in,
                              void* d_out, int out_size) {
    const float4* x   = (const float4*)d_in[0];
    const int*    row = (const int*)d_in[1];
    const int*    col = (const int*)d_in[2];
    const float*  w   = (const float*)d_in[3];

    int N  = in_sizes[0] / 16;   // 100000
    int E  = in_sizes[1];        // 3200000
    int n4 = N * 4;

    float4* out = (float4*)d_out;

    // Zero fp16 accumulators via memset node (overlaps pack launch).
    void* aggPtr = nullptr;
    cudaGetSymbolAddress(&aggPtr, g_agg16);
    cudaMemsetAsync(aggPtr, 0, (size_t)N * 32);

    pack_kernel<<<(n4 + 255) / 256, 256>>>(x, n4);

    int Eh = (E + 1) >> 1;
    int edgeThreads = 2 * Eh;                  // 2 threads per edge-pair
    int edgeBlocks = (edgeThreads + 255) / 256;
    int copyBlocks = (n4 + 255) / 256;
    edge_copy_kernel<<<edgeBlocks + copyBlocks, 256>>>(x, row, col, w,
                                                       out, n4, E, edgeBlocks);

    final_kernel<<<(n4 + 511) / 512, 256>>>(x, out, n4);
}

// round 14
// speedup vs baseline: 1.0798x; 1.0798x over previous
#include <cuda_runtime.h>
#include <cuda_fp16.h>

// Output layout (flattened jax pytree, each region N*16 f32 = n4 float4s):
//   region 0: -x + tanh(agg)   region 1: x   region 2: -x
//   region 3: agg (f32, from fp16 accumulator)   region 4: tanh(agg)
//
// R14 = R11 (best: ILP=2 edge, fused pack+zero, 1-elem/thread small kernels)
// + PDL overlap: edge kernel's copy blocks (independent of pack) run
// concurrently with pack; edge blocks gridsync first. final PDL-overlaps the
// edge tail. Correctness: cudaGridDependencySynchronize guarantees the
// primary kernel's writes are visible before dependent reads.

#define MAX_N 100000
__device__ uint4 g_x16[MAX_N * 2];    // fp16 copy of x: 32 B/node
__device__ uint4 g_agg16[MAX_N * 2];  // fp16 accumulators: 32 B/node

__device__ __forceinline__ unsigned pack_h2(float a, float b) {
    __half2 h = __floats2half2_rn(a, b);
    return *reinterpret_cast<unsigned*>(&h);
}

__device__ __forceinline__ float2 h2f(unsigned u) {
    __half2 h = *reinterpret_cast<__half2*>(&u);
    return __half22float2(h);
}

// Pack x -> fp16 and zero the fp16 accumulators (one pass, R11 shape).
__global__ void pack_kernel(const float4* __restrict__ x, int n4, int n2) {
    cudaTriggerProgrammaticLaunchCompletion();   // let edge grid start early
    int i = blockIdx.x * blockDim.x + threadIdx.x;
    if (i < n2) g_agg16[i] = make_uint4(0u, 0u, 0u, 0u);
    if (i >= n4) return;
    float4 v = __ldg(&x[i]);
    ((uint2*)g_x16)[i] = make_uint2(pack_h2(v.x, v.y), pack_h2(v.z, v.w));
}

__device__ __forceinline__ void msgs(float we, const uint4& ur, const uint4& uc,
                                     unsigned& p0, unsigned& p1,
                                     unsigned& p2, unsigned& p3) {
    float2 a0 = h2f(ur.x), a1 = h2f(ur.y), a2 = h2f(ur.z), a3 = h2f(ur.w);
    float2 b0 = h2f(uc.x), b1 = h2f(uc.y), b2 = h2f(uc.z), b3 = h2f(uc.w);
    p0 = pack_h2(we * __sinf(a0.x - b0.x), we * __sinf(a0.y - b0.y));
    p1 = pack_h2(we * __sinf(a1.x - b1.x), we * __sinf(a1.y - b1.y));
    p2 = pack_h2(we * __sinf(a2.x - b2.x), we * __sinf(a2.y - b2.y));
    p3 = pack_h2(we * __sinf(a3.x - b3.x), we * __sinf(a3.y - b3.y));
}

#define RED_V4F16X2(dst, p0, p1, p2, p3)                                    \
    asm volatile("red.global.add.noftz.v4.f16x2 [%0], {%1, %2, %3, %4};"    \
                 :: "l"(dst), "r"(p0), "r"(p1), "r"(p2), "r"(p3) : "memory")

// Copy blocks FIRST (no dependency on pack -> no gridsync -> overlap pack);
// edge blocks gridsync, then R11 body (2 edges/thread, 2 threads/edge).
__global__ void edge_copy_kernel(const float4* __restrict__ x,
                                 const int* __restrict__ row,
                                 const int* __restrict__ col,
                                 const float* __restrict__ w,
                                 float4* __restrict__ out,
                                 int n4, int E, int copyBlocks) {
    if (blockIdx.x < copyBlocks) {
        int i = blockIdx.x * blockDim.x + threadIdx.x;
        if (i < n4) {
            float4 v = __ldg(&x[i]);
            __stcs(&out[n4 + i], v);                                      // region 1
            __stcs(&out[2 * n4 + i],
                   make_float4(-v.x, -v.y, -v.z, -v.w));                  // region 2
        }
        return;
    }

    cudaGridDependencySynchronize();   // pack's g_x16 / g_agg16 now visible

    int t = (blockIdx.x - copyBlocks) * blockDim.x + threadIdx.x;
    int p = t >> 1;                  // pair index: edges p and p+Eh
    int h = t & 1;                   // lane-pair half: 8 dims each
    int Eh = (E + 1) >> 1;
    if (p >= Eh) return;
    int eB = p + Eh;
    bool hasB = eB < E;

    int   rA = __ldg(&row[p]);
    int   cA = __ldg(&col[p]);
    float wA = __ldg(&w[p]);
    int rB = rA, cB = cA; float wB = 0.f;
    if (hasB) { rB = __ldg(&row[eB]); cB = __ldg(&col[eB]); wB = __ldg(&w[eB]); }

    // Front-batch 4 independent 16 B gathers (MLP=4); lanes 2i/2i+1 of an
    // edge hit the same 32 B record -> 1 combined wavefront per endpoint.
    uint4 urA = __ldg(&g_x16[rA * 2 + h]);
    uint4 ucA = __ldg(&g_x16[cA * 2 + h]);
    uint4 urB = __ldg(&g_x16[rB * 2 + h]);
    uint4 ucB = __ldg(&g_x16[cB * 2 + h]);

    unsigned pa0, pa1, pa2, pa3, pb0, pb1, pb2, pb3;
    msgs(wA, urA, ucA, pa0, pa1, pa2, pa3);
    msgs(wB, urB, ucB, pb0, pb1, pb2, pb3);

    RED_V4F16X2(&g_agg16[cA * 2 + h], pa0, pa1, pa2, pa3);
    if (hasB) RED_V4F16X2(&g_agg16[cB * 2 + h], pb0, pb1, pb2, pb3);
}

// Final (R11 1-elem/thread shape) + gridsync so it can PDL-overlap edge tail.
__global__ void final_kernel(const float4* __restrict__ x,
                             float4* __restrict__ out, int n4) {
    cudaGridDependencySynchronize();   // all REDs visible
    int i = blockIdx.x * blockDim.x + threadIdx.x;
    if (i >= n4) return;
    uint2 a16 = ((const uint2*)g_agg16)[i];     // 4 halves (L2-resident)
    float2 lo = h2f(a16.x), hi = h2f(a16.y);
    float4 a = make_float4(lo.x, lo.y, hi.x, hi.y);
    float4 v = __ldg(&x[i]);
    float4 t;
    t.x = tanhf(a.x); t.y = tanhf(a.y); t.z = tanhf(a.z); t.w = tanhf(a.w);
    __stcs(&out[3 * n4 + i], a);                                          // region 3
    __stcs(&out[4 * n4 + i], t);                                          // region 4
    __stcs(&out[i],
           make_float4(t.x - v.x, t.y - v.y, t.z - v.z, t.w - v.w));      // region 0
}

extern "C" void kernel_launch(void* const* d_in, const int* in_sizes, int n_in,
                              void* d_out, int out_size) {
    const float4* x   = (const float4*)d_in[0];
    const int*    row = (const int*)d_in[1];
    const int*    col = (const int*)d_in[2];
    const float*  w   = (const float*)d_in[3];

    int N  = in_sizes[0] / 16;   // 100000
    int E  = in_sizes[1];        // 3200000
    int n4 = N * 4;
    int n2 = N * 2;

    float4* out = (float4*)d_out;

    pack_kernel<<<(n4 + 255) / 256, 256>>>(x, n4, n2);

    cudaLaunchAttribute pdl[1];
    pdl[0].id = cudaLaunchAttributeProgrammaticStreamSerialization;
    pdl[0].val.programmaticStreamSerializationAllowed = 1;

    int Eh = (E + 1) >> 1;
    int edgeThreads = 2 * Eh;                  // 2 threads per edge-pair
    int edgeBlocks = (edgeThreads + 255) / 256;
    int copyBlocks = (n4 + 255) / 256;

    {
        cudaLaunchConfig_t cfg = {};
        cfg.gridDim  = dim3(copyBlocks + edgeBlocks);
        cfg.blockDim = dim3(256);
        cfg.stream   = 0;
        cfg.attrs    = pdl;
        cfg.numAttrs = 1;
        cudaLaunchKernelEx(&cfg, edge_copy_kernel,
                           x, row, col, w, out, n4, E, copyBlocks);
    }
    {
        cudaLaunchConfig_t cfg = {};
        cfg.gridDim  = dim3((n4 + 255) / 256);
        cfg.blockDim = dim3(256);
        cfg.stream   = 0;
        cfg.attrs    = pdl;
        cfg.numAttrs = 1;
        cudaLaunchKernelEx(&cfg, final_kernel, x, out, n4);
    }
}